// round 6
// baseline (speedup 1.0000x reference)
#include <cuda_runtime.h>
#include <cuda_bf16.h>
#include <cuda_fp16.h>
#include <cstdint>

// ---------------------------------------------------------------- constants
#define N_NODES 50000
#define K_DIM   512
#define OUTC    512
#define DEG     32
#define E_EDGES (N_NODES * DEG)

#define TM 128
#define TN 128
#define TKC 32                 // K per pipeline chunk
#define NKC (K_DIM / TKC)      // 16 chunks
#define M_TILES ((N_NODES + TM - 1) / TM)   // 391
#define GEMM_CTAS (M_TILES * 4)             // 1564

// SMEM: rows padded to 80B -> conflict-free ldmatrix. 3 tiles per stage:
// A (x), B_HI (w_hi), B_LO (wc_lo, alpha only). 3 stages -> 92160 B, 2 CTAs/SM.
// Alpha epilogue reuses the same smem as a 128x132 fp32 tile (67584 B).
#define ROWB     80
#define TILE_B   (128 * ROWB)      // 10240
#define A_T      0
#define B_HI     (1 * TILE_B)
#define B_LO     (2 * TILE_B)
#define STAGE_SZ (3 * TILE_B)      // 30720
#define NSTAGE   3
#define SMEM_TOTAL (NSTAGE * STAGE_SZ)  // 92160
#define PITCH    132               // fp32 pitch for alpha staging tile

// ---------------------------------------------------------------- scratch
__device__ __half g_xh[(size_t)N_NODES * K_DIM];          // fp16(x)
__device__ __nv_bfloat16 g_beta[(size_t)N_NODES * OUTC];
__device__ __half g_Bhi[(size_t)2 * OUTC * K_DIM];        // [o][k]: o<512 wc_hi, else wn_hi
__device__ __half g_Blo[(size_t)OUTC * K_DIM];            // wc_lo (alpha correction)
__device__ int g_is64;

// ---------------------------------------------------------------- helpers
__device__ __forceinline__ uint32_t smem_to_u32(const void* p) {
    uint32_t a;
    asm("{ .reg .u64 t; cvta.to.shared.u64 t, %1; cvt.u32.u64 %0, t; }" : "=r"(a) : "l"(p));
    return a;
}

#define CP_ASYNC16(dst, src) \
    asm volatile("cp.async.cg.shared.global [%0], [%1], 16;" :: "r"((uint32_t)(dst)), "l"(src))
#define CP_COMMIT() asm volatile("cp.async.commit_group;" ::: "memory")

__device__ __forceinline__ void ldsm4(uint32_t* r, uint32_t addr) {
    asm volatile("ldmatrix.sync.aligned.m8n8.x4.shared.b16 {%0,%1,%2,%3}, [%4];"
                 : "=r"(r[0]), "=r"(r[1]), "=r"(r[2]), "=r"(r[3]) : "r"(addr));
}

__device__ __forceinline__ void mma16816(float* c, const uint32_t* a,
                                         uint32_t b0, uint32_t b1) {
    asm volatile(
        "mma.sync.aligned.m16n8k16.row.col.f32.f16.f16.f32 "
        "{%0,%1,%2,%3}, {%4,%5,%6,%7}, {%8,%9}, {%0,%1,%2,%3};"
        : "+f"(c[0]), "+f"(c[1]), "+f"(c[2]), "+f"(c[3])
        : "r"(a[0]), "r"(a[1]), "r"(a[2]), "r"(a[3]), "r"(b0), "r"(b1));
}

// ---------------------------------------------------------------- prep kernels
__global__ void prep_x_kernel(const float* __restrict__ x) {
    size_t i = ((size_t)blockIdx.x * blockDim.x + threadIdx.x) * 4;
    float4 v = *reinterpret_cast<const float4*>(x + i);
    __half2* p = reinterpret_cast<__half2*>(g_xh + i);
    p[0] = __floats2half2_rn(v.x, v.y);
    p[1] = __floats2half2_rn(v.z, v.w);
}

__global__ void prep_w_kernel(const float* __restrict__ wc, const float* __restrict__ wn) {
    int idx = blockIdx.x * blockDim.x + threadIdx.x;   // idx = o*512 + k
    int o = idx >> 9;
    int k = idx & 511;
    if (o < OUTC) {
        float v = wc[k * OUTC + o];
        __half h = __float2half_rn(v);
        g_Bhi[idx] = h;
        g_Blo[idx] = __float2half_rn(v - __half2float(h));
    } else {
        g_Bhi[idx] = __float2half_rn(wn[k * OUTC + (o - OUTC)]);
    }
}

// src = repeat(arange(N), 32): src[32]==1 in int64 layout; as int32 pairs the
// same 8 bytes at u64-index 32 hold {2,2}, never 1.
__global__ void detect_kernel(const void* __restrict__ e) {
    if (threadIdx.x == 0) {
        unsigned long long v = reinterpret_cast<const unsigned long long*>(e)[32];
        g_is64 = (v == 1ULL) ? 1 : 0;
    }
}

// ---------------------------------------------------------------- GEMM mainloop
__device__ __forceinline__ void load_stage(uint32_t sbase, int tid, int m0, int n0,
                                           int kc, bool isAlpha) {
    const int k0 = kc * TKC;
    #pragma unroll
    for (int i = 0; i < 2; i++) {
        int ch = tid + i * 256;             // 0..511
        int row = ch >> 2, col = ch & 3;    // 128 rows x 4 x 16B
        int m = m0 + row; if (m > N_NODES - 1) m = N_NODES - 1;
        uint32_t dst = sbase + (uint32_t)(row * ROWB + col * 16);
        const char* srcA = reinterpret_cast<const char*>(g_xh + (size_t)m * K_DIM + k0) + col * 16;
        CP_ASYNC16(dst + A_T, srcA);
        const char* srcB = reinterpret_cast<const char*>(g_Bhi + (size_t)(n0 + row) * K_DIM + k0) + col * 16;
        CP_ASYNC16(dst + B_HI, srcB);
        if (isAlpha) {
            const char* srcBl = reinterpret_cast<const char*>(g_Blo + (size_t)(n0 + row) * K_DIM + k0) + col * 16;
            CP_ASYNC16(dst + B_LO, srcBl);
        }
    }
    CP_COMMIT();
}

// Fills c[2][8][4]. IS_ALPHA: 2-pass (wc_hi + wc_lo); else 1-pass (wn_hi).
template <bool IS_ALPHA>
__device__ __forceinline__ void gemm_main(uint32_t sb, int m0, int n0,
                                          float c[2][8][4]) {
    const int tid = threadIdx.x, wid = tid >> 5, lane = tid & 31;
    const int wm = wid & 3, wn = wid >> 2;          // warp: 32(M) x 64(N)

    #pragma unroll
    for (int a = 0; a < 2; a++)
        #pragma unroll
        for (int b = 0; b < 8; b++)
            #pragma unroll
            for (int q = 0; q < 4; q++) c[a][b][q] = 0.0f;

    const uint32_t lrow = (uint32_t)(lane & 15);
    const uint32_t lcol = (uint32_t)(lane >> 4) * 16;
    const uint32_t aOff = (uint32_t)((wm * 32 + lrow) * ROWB) + lcol;
    const uint32_t bOff = (uint32_t)((wn * 64 + lrow) * ROWB) + lcol;

    load_stage(sb + 0 * STAGE_SZ, tid, m0, n0, 0, IS_ALPHA);
    load_stage(sb + 1 * STAGE_SZ, tid, m0, n0, 1, IS_ALPHA);

    #pragma unroll 1
    for (int kc = 0; kc < NKC; kc++) {
        if (kc == NKC - 1) asm volatile("cp.async.wait_group 0;" ::: "memory");
        else               asm volatile("cp.async.wait_group 1;" ::: "memory");
        __syncthreads();   // chunk kc visible; all warps done with chunk kc-1

        if (kc + 2 < NKC)
            load_stage(sb + (uint32_t)(((kc + 2) % NSTAGE) * STAGE_SZ), tid, m0, n0,
                       kc + 2, IS_ALPHA);

        const uint32_t stage = sb + (uint32_t)((kc % NSTAGE) * STAGE_SZ);
        #pragma unroll
        for (int ks = 0; ks < 2; ks++) {
            const uint32_t kb = (uint32_t)(ks * 32);
            uint32_t ah0[4], ah1[4];
            ldsm4(ah0, stage + A_T + aOff + kb);
            ldsm4(ah1, stage + A_T + aOff + 16 * ROWB + kb);
            #pragma unroll
            for (int nfp = 0; nfp < 4; nfp++) {
                const int nf0 = nfp * 2, nf1 = nfp * 2 + 1;
                uint32_t bh[4];
                ldsm4(bh, stage + B_HI + bOff + (uint32_t)(nfp * 16 * ROWB) + kb);
                mma16816(c[0][nf0], ah0, bh[0], bh[2]);
                mma16816(c[1][nf0], ah1, bh[0], bh[2]);
                mma16816(c[0][nf1], ah0, bh[1], bh[3]);
                mma16816(c[1][nf1], ah1, bh[1], bh[3]);
                if (IS_ALPHA) {
                    uint32_t bl[4];
                    ldsm4(bl, stage + B_LO + bOff + (uint32_t)(nfp * 16 * ROWB) + kb);
                    mma16816(c[0][nf0], ah0, bl[0], bl[2]);
                    mma16816(c[1][nf0], ah1, bl[0], bl[2]);
                    mma16816(c[0][nf1], ah0, bl[1], bl[3]);
                    mma16816(c[1][nf1], ah1, bl[1], bl[3]);
                }
            }
        }
    }
}

// ---------------------------------------------------------------- k1: beta GEMM
__global__ void __launch_bounds__(256, 2)
beta_gemm_kernel() {
    extern __shared__ char smem[];
    const uint32_t sb = smem_to_u32(smem);
    const int mt = blockIdx.x >> 2, nt = blockIdx.x & 3;
    const int m0 = mt * TM;

    float c[2][8][4];
    gemm_main<false>(sb, m0, (nt + 4) * TN, c);

    const int lane = threadIdx.x & 31, wid = threadIdx.x >> 5;
    const int wm = wid & 3, wn = wid >> 2;
    const int t4 = lane >> 2, t2 = (lane & 3) * 2;
    const int colBase = nt * TN + wn * 64;

    #pragma unroll
    for (int mf = 0; mf < 2; mf++) {
        const int mLo = m0 + wm * 32 + mf * 16 + t4;
        const int mHi = mLo + 8;
        #pragma unroll
        for (int nf = 0; nf < 8; nf++) {
            const int col = colBase + nf * 8 + t2;
            const float* cc = c[mf][nf];
            if (mLo < N_NODES)
                *reinterpret_cast<__nv_bfloat162*>(g_beta + (size_t)mLo * OUTC + col) =
                    __floats2bfloat162_rn(cc[0], cc[1]);
            if (mHi < N_NODES)
                *reinterpret_cast<__nv_bfloat162*>(g_beta + (size_t)mHi * OUTC + col) =
                    __floats2bfloat162_rn(cc[2], cc[3]);
        }
    }
}

// ---------------------------------------------------------------- k2: alpha GEMM + fused gather
__global__ void __launch_bounds__(256, 2)
alpha_gather_kernel(const float* __restrict__ bias, const void* __restrict__ edges,
                    float* __restrict__ out) {
    extern __shared__ char smem[];
    const uint32_t sb = smem_to_u32(smem);
    const int mt = blockIdx.x >> 2, nt = blockIdx.x & 3;
    const int m0 = mt * TM;
    const int tid = threadIdx.x, wid = tid >> 5, lane = tid & 31;

    float c[2][8][4];
    gemm_main<true>(sb, m0, nt * TN, c);

    // ---- stage 1: alpha + bias -> smem fp32 tile [128 x 128], pitch 132
    __syncthreads();   // all warps done reading pipeline smem
    float* sf = reinterpret_cast<float*>(smem);
    {
        const int wm = wid & 3, wn = wid >> 2;
        const int t4 = lane >> 2, t2 = (lane & 3) * 2;
        const int colL = wn * 64;                 // tile-local column base
        #pragma unroll
        for (int mf = 0; mf < 2; mf++) {
            const int rLo = wm * 32 + mf * 16 + t4;   // tile-local rows
            #pragma unroll
            for (int nf = 0; nf < 8; nf++) {
                const int col = colL + nf * 8 + t2;
                const float2 bv = *reinterpret_cast<const float2*>(bias + nt * TN + col);
                const float* cc = c[mf][nf];
                *reinterpret_cast<float2*>(sf + rLo * PITCH + col) =
                    make_float2(cc[0] + bv.x, cc[1] + bv.y);
                *reinterpret_cast<float2*>(sf + (rLo + 8) * PITCH + col) =
                    make_float2(cc[2] + bv.x, cc[3] + bv.y);
            }
        }
    }
    __syncthreads();

    // ---- stage 2: gather-mean over this tile's 128-col slice, write out once
    const int is64 = g_is64;
    const float inv = 1.0f / 32.0f;
    const __nv_bfloat16* betaCol = g_beta + nt * TN;

    #pragma unroll 1
    for (int i = 0; i < 16; i++) {
        const int nloc = wid * 16 + i;
        const int n = m0 + nloc;
        if (n >= N_NODES) break;

        const long long epos = (long long)E_EDGES + (long long)n * DEG + lane;
        int idx;
        if (is64) idx = (int)reinterpret_cast<const long long*>(edges)[epos];
        else      idx = reinterpret_cast<const int*>(edges)[epos];

        float a0 = 0.f, a1 = 0.f, a2 = 0.f, a3 = 0.f;
        #pragma unroll 4
        for (int j = 0; j < DEG; j++) {
            const int t = __shfl_sync(0xFFFFFFFFu, idx, j);
            const uint2 u = __ldg(reinterpret_cast<const uint2*>(
                                      betaCol + (size_t)t * OUTC) + lane);
            const float2 f0 = __bfloat1622float2(reinterpret_cast<const __nv_bfloat162&>(u.x));
            const float2 f1 = __bfloat1622float2(reinterpret_cast<const __nv_bfloat162&>(u.y));
            a0 += f0.x; a1 += f0.y; a2 += f1.x; a3 += f1.y;
        }

        const float4 al = *reinterpret_cast<const float4*>(sf + nloc * PITCH + lane * 4);
        float4 v = make_float4(al.x + a0 * inv, al.y + a1 * inv,
                               al.z + a2 * inv, al.w + a3 * inv);
        *reinterpret_cast<float4*>(out + (size_t)n * OUTC + nt * TN + lane * 4) = v;
    }
}

// ---------------------------------------------------------------- launch
extern "C" void kernel_launch(void* const* d_in, const int* in_sizes, int n_in,
                              void* d_out, int out_size) {
    const float* x    = (const float*)d_in[0];
    const float* wc   = (const float*)d_in[1];
    const float* wn   = (const float*)d_in[2];
    const float* bias = (const float*)d_in[3];
    const void*  edges = d_in[4];
    float* out = (float*)d_out;

    static int smem_set = 0;
    if (!smem_set) {
        cudaFuncSetAttribute(beta_gemm_kernel, cudaFuncAttributeMaxDynamicSharedMemorySize, SMEM_TOTAL);
        cudaFuncSetAttribute(alpha_gather_kernel, cudaFuncAttributeMaxDynamicSharedMemorySize, SMEM_TOTAL);
        smem_set = 1;
    }

    prep_x_kernel<<<(N_NODES * K_DIM) / (256 * 4), 256>>>(x);
    prep_w_kernel<<<(2 * OUTC * K_DIM) / 256, 256>>>(wc, wn);
    detect_kernel<<<1, 32>>>(edges);
    beta_gemm_kernel<<<GEMM_CTAS, 256, SMEM_TOTAL>>>();
    alpha_gather_kernel<<<GEMM_CTAS, 256, SMEM_TOTAL>>>(bias, edges, out);
}

// round 7
// speedup vs baseline: 1.7460x; 1.7460x over previous
#include <cuda_runtime.h>
#include <cuda_fp16.h>
#include <cstdint>

// ---------------------------------------------------------------- constants
#define N_NODES 50000
#define K_DIM   512
#define OUTC    512
#define NTOT    1024          // [alpha(512) | beta(512)] fused output columns
#define DEG     32
#define E_EDGES (N_NODES * DEG)

#define TM 128
#define TN 128
#define TKC 32                 // K per pipeline chunk
#define NKC (K_DIM / TKC)      // 16 chunks
#define M_TILES ((N_NODES + TM - 1) / TM)   // 391
#define N_TILES (NTOT / TN)                 // 8

// SMEM: rows padded to 80B (32 fp16 data + 16B pad) -> conflict-free ldmatrix.
// 2 tiles per stage (A, B). 4 stages x 20480 = 81920 B -> 2 CTAs/SM.
#define ROWB     80
#define TILE_B   (128 * ROWB)      // 10240
#define A_T      0
#define B_T      (1 * TILE_B)
#define STAGE_SZ (2 * TILE_B)      // 20480
#define NSTAGE   4
#define SMEM_TOTAL (NSTAGE * STAGE_SZ)  // 81920

// ---------------------------------------------------------------- scratch
__device__ __half g_xh[(size_t)N_NODES * K_DIM];       // fp16(x)
__device__ __half g_beta[(size_t)N_NODES * OUTC];      // fp16 beta
__device__ __half g_Bh[(size_t)NTOT * K_DIM];          // [o][k]: o<512 wc, else wn
__device__ int g_is64;

// ---------------------------------------------------------------- helpers
__device__ __forceinline__ uint32_t smem_to_u32(const void* p) {
    uint32_t a;
    asm("{ .reg .u64 t; cvta.to.shared.u64 t, %1; cvt.u32.u64 %0, t; }" : "=r"(a) : "l"(p));
    return a;
}

#define CP_ASYNC16(dst, src) \
    asm volatile("cp.async.cg.shared.global [%0], [%1], 16;" :: "r"((uint32_t)(dst)), "l"(src))
#define CP_COMMIT() asm volatile("cp.async.commit_group;" ::: "memory")

__device__ __forceinline__ void ldsm4(uint32_t* r, uint32_t addr) {
    asm volatile("ldmatrix.sync.aligned.m8n8.x4.shared.b16 {%0,%1,%2,%3}, [%4];"
                 : "=r"(r[0]), "=r"(r[1]), "=r"(r[2]), "=r"(r[3]) : "r"(addr));
}

__device__ __forceinline__ void mma16816(float* c, const uint32_t* a,
                                         uint32_t b0, uint32_t b1) {
    asm volatile(
        "mma.sync.aligned.m16n8k16.row.col.f32.f16.f16.f32 "
        "{%0,%1,%2,%3}, {%4,%5,%6,%7}, {%8,%9}, {%0,%1,%2,%3};"
        : "+f"(c[0]), "+f"(c[1]), "+f"(c[2]), "+f"(c[3])
        : "r"(a[0]), "r"(a[1]), "r"(a[2]), "r"(a[3]), "r"(b0), "r"(b1));
}

// ---------------------------------------------------------------- prep kernels
__global__ void prep_x_kernel(const float* __restrict__ x) {
    size_t i = ((size_t)blockIdx.x * blockDim.x + threadIdx.x) * 4;
    float4 v = *reinterpret_cast<const float4*>(x + i);
    __half2* p = reinterpret_cast<__half2*>(g_xh + i);
    p[0] = __floats2half2_rn(v.x, v.y);
    p[1] = __floats2half2_rn(v.z, v.w);
}

__global__ void prep_w_kernel(const float* __restrict__ wc, const float* __restrict__ wn) {
    int idx = blockIdx.x * blockDim.x + threadIdx.x;   // idx = o*512 + k
    int o = idx >> 9;
    int k = idx & 511;
    float v = (o < OUTC) ? wc[k * OUTC + o] : wn[k * OUTC + (o - OUTC)];
    g_Bh[idx] = __float2half_rn(v);
}

// src = repeat(arange(N), 32): src[32]==1 in int64 layout; as int32 pairs the
// same 8 bytes at u64-index 32 hold {2,2}, never 1.
__global__ void detect_kernel(const void* __restrict__ e) {
    if (threadIdx.x == 0) {
        unsigned long long v = reinterpret_cast<const unsigned long long*>(e)[32];
        g_is64 = (v == 1ULL) ? 1 : 0;
    }
}

// ---------------------------------------------------------------- GEMM
__device__ __forceinline__ void load_stage(uint32_t sbase, int tid, int m0, int n0, int kc) {
    const int k0 = kc * TKC;
    #pragma unroll
    for (int i = 0; i < 2; i++) {
        int ch = tid + i * 256;             // 0..511
        int row = ch >> 2, col = ch & 3;    // 128 rows x 4 x 16B
        int m = m0 + row; if (m > N_NODES - 1) m = N_NODES - 1;
        uint32_t dst = sbase + (uint32_t)(row * ROWB + col * 16);
        const char* srcA = reinterpret_cast<const char*>(g_xh + (size_t)m * K_DIM + k0) + col * 16;
        CP_ASYNC16(dst + A_T, srcA);
        const char* srcB = reinterpret_cast<const char*>(g_Bh + (size_t)(n0 + row) * K_DIM + k0) + col * 16;
        CP_ASYNC16(dst + B_T, srcB);
    }
    CP_COMMIT();
}

__global__ void __launch_bounds__(256, 2)
gemm_kernel(const float* __restrict__ bias, float* __restrict__ out) {
    extern __shared__ char smem[];
    const uint32_t sb = smem_to_u32(smem);
    const int tid = threadIdx.x, wid = tid >> 5, lane = tid & 31;
    const int mt = blockIdx.x >> 3, nt = blockIdx.x & 7;
    const int m0 = mt * TM, n0 = nt * TN;
    const int wm = wid & 3, wn = wid >> 2;     // warp: 32(M) x 64(N)
    const bool isAlpha = (nt < 4);

    float c[2][8][4];
    #pragma unroll
    for (int a = 0; a < 2; a++)
        #pragma unroll
        for (int b = 0; b < 8; b++)
            #pragma unroll
            for (int q = 0; q < 4; q++) c[a][b][q] = 0.0f;

    // per-thread ldmatrix base offsets (row t&15, column-half t>>4)
    const uint32_t lrow = (uint32_t)(lane & 15);
    const uint32_t lcol = (uint32_t)(lane >> 4) * 16;
    const uint32_t aOff = (uint32_t)((wm * 32 + lrow) * ROWB) + lcol;
    const uint32_t bOff = (uint32_t)((wn * 64 + lrow) * ROWB) + lcol;

    load_stage(sb + 0 * STAGE_SZ, tid, m0, n0, 0);
    load_stage(sb + 1 * STAGE_SZ, tid, m0, n0, 1);
    load_stage(sb + 2 * STAGE_SZ, tid, m0, n0, 2);

    #pragma unroll 1
    for (int kc = 0; kc < NKC; kc++) {
        if (kc < NKC - 2)       asm volatile("cp.async.wait_group 2;" ::: "memory");
        else if (kc == NKC - 2) asm volatile("cp.async.wait_group 1;" ::: "memory");
        else                    asm volatile("cp.async.wait_group 0;" ::: "memory");
        __syncthreads();   // chunk kc visible; all warps done with chunk kc-1

        // prefetch kc+3 into the stage freed at iter kc-1 (guarded by barrier above)
        if (kc + 3 < NKC)
            load_stage(sb + (uint32_t)(((kc + 3) % NSTAGE) * STAGE_SZ), tid, m0, n0, kc + 3);

        const uint32_t stage = sb + (uint32_t)((kc % NSTAGE) * STAGE_SZ);
        #pragma unroll
        for (int ks = 0; ks < 2; ks++) {
            const uint32_t kb = (uint32_t)(ks * 32);
            uint32_t ah0[4], ah1[4];
            ldsm4(ah0, stage + A_T + aOff + kb);
            ldsm4(ah1, stage + A_T + aOff + 16 * ROWB + kb);
            #pragma unroll
            for (int nfp = 0; nfp < 4; nfp++) {
                const int nf0 = nfp * 2, nf1 = nfp * 2 + 1;
                uint32_t bh[4];
                ldsm4(bh, stage + B_T + bOff + (uint32_t)(nfp * 16 * ROWB) + kb);
                mma16816(c[0][nf0], ah0, bh[0], bh[2]);
                mma16816(c[1][nf0], ah1, bh[0], bh[2]);
                mma16816(c[0][nf1], ah0, bh[1], bh[3]);
                mma16816(c[1][nf1], ah1, bh[1], bh[3]);
            }
        }
    }

    // --------------------------- epilogue (straight from C fragments)
    const int t4 = lane >> 2;            // row within 8
    const int t2 = (lane & 3) * 2;       // col pair
    const int colBase = (isAlpha ? nt : nt - 4) * TN + wn * 64;

    #pragma unroll
    for (int mf = 0; mf < 2; mf++) {
        const int mLo = m0 + wm * 32 + mf * 16 + t4;
        const int mHi = mLo + 8;
        #pragma unroll
        for (int nf = 0; nf < 8; nf++) {
            const int col = colBase + nf * 8 + t2;
            const float* cc = c[mf][nf];
            if (isAlpha) {
                const float2 bv = *reinterpret_cast<const float2*>(bias + col);
                if (mLo < N_NODES)
                    *reinterpret_cast<float2*>(out + (size_t)mLo * OUTC + col) =
                        make_float2(cc[0] + bv.x, cc[1] + bv.y);
                if (mHi < N_NODES)
                    *reinterpret_cast<float2*>(out + (size_t)mHi * OUTC + col) =
                        make_float2(cc[2] + bv.x, cc[3] + bv.y);
            } else {
                if (mLo < N_NODES)
                    *reinterpret_cast<__half2*>(g_beta + (size_t)mLo * OUTC + col) =
                        __floats2half2_rn(cc[0], cc[1]);
                if (mHi < N_NODES)
                    *reinterpret_cast<__half2*>(g_beta + (size_t)mHi * OUTC + col) =
                        __floats2half2_rn(cc[2], cc[3]);
            }
        }
    }
}

// ---------------------------------------------------------------- gather-mean
__device__ __forceinline__ void acc8h(float* a, uint4 u) {
    float2 f;
    f = __half22float2(reinterpret_cast<__half2&>(u.x)); a[0] += f.x; a[1] += f.y;
    f = __half22float2(reinterpret_cast<__half2&>(u.y)); a[2] += f.x; a[3] += f.y;
    f = __half22float2(reinterpret_cast<__half2&>(u.z)); a[4] += f.x; a[5] += f.y;
    f = __half22float2(reinterpret_cast<__half2&>(u.w)); a[6] += f.x; a[7] += f.y;
}

__global__ void __launch_bounds__(256)
gather_kernel(const void* __restrict__ edges, float* __restrict__ out) {
    const int warp = threadIdx.x >> 5, lane = threadIdx.x & 31;
    const int n = blockIdx.x * 8 + warp;
    if (n >= N_NODES) return;

    const long long epos = (long long)E_EDGES + (long long)n * DEG + lane;
    int idx;
    if (g_is64) idx = (int)reinterpret_cast<const long long*>(edges)[epos];
    else        idx = reinterpret_cast<const int*>(edges)[epos];

    float acc[16];
    #pragma unroll
    for (int i = 0; i < 16; i++) acc[i] = 0.0f;

    #pragma unroll 4
    for (int j = 0; j < DEG; j++) {
        const int t = __shfl_sync(0xFFFFFFFFu, idx, j);
        const uint4* row = reinterpret_cast<const uint4*>(g_beta + (size_t)t * OUTC) + lane * 2;
        uint4 u = __ldg(row);
        uint4 v = __ldg(row + 1);
        acc8h(acc, u);
        acc8h(acc + 8, v);
    }

    const float inv = 1.0f / 32.0f;
    float4* o = reinterpret_cast<float4*>(out + (size_t)n * OUTC) + lane * 4;
    #pragma unroll
    for (int q = 0; q < 4; q++) {
        float4 t = o[q];
        t.x += acc[q * 4 + 0] * inv;
        t.y += acc[q * 4 + 1] * inv;
        t.z += acc[q * 4 + 2] * inv;
        t.w += acc[q * 4 + 3] * inv;
        o[q] = t;
    }
}

// ---------------------------------------------------------------- launch
extern "C" void kernel_launch(void* const* d_in, const int* in_sizes, int n_in,
                              void* d_out, int out_size) {
    const float* x    = (const float*)d_in[0];
    const float* wc   = (const float*)d_in[1];
    const float* wn   = (const float*)d_in[2];
    const float* bias = (const float*)d_in[3];
    const void*  edges = d_in[4];
    float* out = (float*)d_out;

    static int smem_set = 0;
    if (!smem_set) {
        cudaFuncSetAttribute(gemm_kernel, cudaFuncAttributeMaxDynamicSharedMemorySize, SMEM_TOTAL);
        smem_set = 1;
    }

    prep_x_kernel<<<(N_NODES * K_DIM) / (256 * 4), 256>>>(x);
    prep_w_kernel<<<(NTOT * K_DIM) / 256, 256>>>(wc, wn);
    detect_kernel<<<1, 32>>>(edges);
    gemm_kernel<<<M_TILES * N_TILES, 256, SMEM_TOTAL>>>(bias, out);
    gather_kernel<<<N_NODES / 8, 256>>>(edges, out);
}